// round 9
// baseline (speedup 1.0000x reference)
#include <cuda_runtime.h>
#include <math.h>

#define Bn   4
#define CIN  256
#define CE   64
#define Gn   4
#define Hn   80
#define Wn   80
#define Nn   (Hn*Wn)        // 6400
#define NCH  65             // channel chunks of 4 (16 per group + 1 norm chunk)
#define EPSV 1e-8f
#define TU   512            // threads for k_up / k_down
#define QU   13             // ceil(Nn/TU)

// ---------------- static device scratch ----------------
__device__ float  g_ft   [Bn*Nn*CIN];     // feature transposed (b, n, c)
__device__ float  g_embt [Bn*Nn*CE];
__device__ float  g_gembt[Bn*Nn*CE];
__device__ float  g_conf [Bn*Nn*Gn];      // (b, n, g) float4-readable
__device__ float  g_w    [Bn*Gn*Nn];      // (b, g, k) BFS order
__device__ float4 g_cC   [Bn*NCH*Nn];     // chunked scan data [b][chunk][k] (4 ch)
__device__ float4 g_jm4  [Bn*5*Nn];       // multipliers float4 [b][slot][k]   (norm chunk)
__device__ float  g_jmP  [Bn*5*Gn*Nn];    // multipliers planar [b][slot][g][k] (scalar chunks)
__device__ int    g_janc [Bn*5*Nn];       // ancestors   [b][slot][k]
__device__ int    g_rs   [Bn*5*Nn];       // descendant-range start [b][slot][k]
__device__ int    g_re   [Bn*5*Nn];       // descendant-range end
__device__ int    g_inv  [Bn*Nn];
__device__ int    g_ls   [Bn*(Nn+2)];
__device__ int    g_nlvl [Bn];

// ---------------- packed f32x2 FMA ----------------
__device__ __forceinline__ void ffma2(unsigned long long &d,
                                      unsigned long long a,
                                      unsigned long long b) {
    asm("fma.rn.f32x2 %0, %1, %2, %0;" : "+l"(d) : "l"(a), "l"(b));
}

// ---------------- K1: skinny GEMMs via packed f32x2 FMA ----------------
__global__ __launch_bounds__(256) void k_gemm(const float* __restrict__ feat,
                                              const float* __restrict__ guide,
                                              const float* __restrict__ We,
                                              const float* __restrict__ Wc,
                                              const float* __restrict__ Wg) {
    __shared__ char smraw[34816];
    float*  xs = reinterpret_cast<float*>(smraw);
    float2* ws = reinterpret_cast<float2*>(smraw + 16384);
    float*  stage = reinterpret_cast<float*>(smraw);

    int tid = threadIdx.x;
    int os = tid >> 5;
    int nq = tid & 31;
    int n0 = blockIdx.x * 128;
    int b  = blockIdx.y;
    int path = blockIdx.z;

    const float* X = (path == 0 ? feat : guide) + (size_t)b * CIN * Nn;

    unsigned long long acc[9][2];
#pragma unroll
    for (int j = 0; j < 9; ++j) { acc[j][0] = 0ull; acc[j][1] = 0ull; }

    for (int kc = 0; kc < 256; kc += 32) {
        const float* Xb = X + (size_t)kc * Nn + n0;
#pragma unroll
        for (int i = tid; i < 1024; i += 256) {
            int kk = i >> 5, c4 = i & 31;
            *reinterpret_cast<float4*>(&xs[kk * 128 + c4 * 4]) =
                *reinterpret_cast<const float4*>(&Xb[(size_t)kk * Nn + c4 * 4]);
        }
#pragma unroll
        for (int i = tid; i < 2304; i += 256) {
            int o = i >> 5, kk = i & 31;
            float v = 0.f;
            if (path == 0) {
                if (o < 64)       v = We[o * 256 + kc + kk];
                else if (o < 68)  v = Wc[(o - 64) * 256 + kc + kk];
            } else {
                if (o < 64)       v = Wg[o * 256 + kc + kk];
            }
            ws[i] = make_float2(v, v);
        }
        __syncthreads();
#pragma unroll 2
        for (int kk = 0; kk < 32; ++kk) {
            float4 x4 = *reinterpret_cast<const float4*>(&xs[kk * 128 + nq * 4]);
            unsigned long long xlo = *reinterpret_cast<unsigned long long*>(&x4.x);
            unsigned long long xhi = *reinterpret_cast<unsigned long long*>(&x4.z);
#pragma unroll
            for (int j = 0; j < 9; ++j) {
                float2 wv = ws[(os * 9 + j) * 32 + kk];
                unsigned long long wp = *reinterpret_cast<unsigned long long*>(&wv);
                ffma2(acc[j][0], xlo, wp);
                ffma2(acc[j][1], xhi, wp);
            }
        }
        __syncthreads();
    }
#pragma unroll
    for (int j = 0; j < 9; ++j) {
        int o = os * 9 + j;
        if (o < 68) {
            float2 lo = *reinterpret_cast<float2*>(&acc[j][0]);
            float2 hi = *reinterpret_cast<float2*>(&acc[j][1]);
            stage[(nq * 4 + 0) * 68 + o] = lo.x;
            stage[(nq * 4 + 1) * 68 + o] = lo.y;
            stage[(nq * 4 + 2) * 68 + o] = hi.x;
            stage[(nq * 4 + 3) * 68 + o] = hi.y;
        }
    }
    __syncthreads();
    float* outt = (path == 0) ? g_embt : g_gembt;
#pragma unroll
    for (int i = tid; i < 2048; i += 256) {
        int n = i >> 4, c4 = i & 15;
        float4 v = *reinterpret_cast<float4*>(&stage[n * 68 + c4 * 4]);
        *reinterpret_cast<float4*>(&outt[((size_t)b * Nn + n0 + n) * 64 + c4 * 4]) = v;
    }
    if (path == 0) {
#pragma unroll
        for (int i = tid; i < 512; i += 256) {
            int n = i >> 2, gg = i & 3;
            float x = stage[n * 68 + 64 + gg];
            g_conf[((size_t)b * Nn + n0 + n) * 4 + gg] = 1.f / (1.f + expf(-x));
        }
    }
}

// ---------------- K2: edge weights, 2 threads per node ----------------
__global__ __launch_bounds__(256) void k_w(const int* __restrict__ order,
                                           const int* __restrict__ parent,
                                           const float* __restrict__ beta) {
    int b = blockIdx.y;
    int idx = blockIdx.x * 256 + threadIdx.x;
    int k = idx >> 1, half = idx & 1;
    if (k >= Nn) return;
    int n1 = order[b * Nn + k];
    int p  = parent[b * Nn + k];
    int n0 = order[b * Nn + p];
    int coff = half * 32;
    const float4* e1 = reinterpret_cast<const float4*>(g_embt  + ((size_t)b * Nn + n1) * 64 + coff);
    const float4* e0 = reinterpret_cast<const float4*>(g_embt  + ((size_t)b * Nn + n0) * 64 + coff);
    const float4* q1 = reinterpret_cast<const float4*>(g_gembt + ((size_t)b * Nn + n1) * 64 + coff);
    const float4* q0 = reinterpret_cast<const float4*>(g_gembt + ((size_t)b * Nn + n0) * 64 + coff);
    float d[2] = {0.f, 0.f};
#pragma unroll
    for (int i = 0; i < 8; ++i) {
        float4 a = e1[i], c = e0[i];
        float dx = a.x - c.x, dy = a.y - c.y, dz = a.z - c.z, dw = a.w - c.w;
        d[i >> 2] += dx * dx + dy * dy + dz * dz + dw * dw;
    }
#pragma unroll
    for (int i = 0; i < 8; ++i) {
        float4 a = q1[i], c = q0[i];
        float dx = a.x - c.x, dy = a.y - c.y, dz = a.z - c.z, dw = a.w - c.w;
        d[i >> 2] += dx * dx + dy * dy + dz * dz + dw * dw;
    }
#pragma unroll
    for (int j = 0; j < 2; ++j) {
        int g = half * 2 + j;
        float bb = beta[g];
        g_w[((size_t)b * 4 + g) * Nn + k] = expf(-(d[j] + bb * bb));
    }
}

// ---------------- K3: fused transpose + levels + jump tables/ranges ----------------
__global__ __launch_bounds__(256) void k_pretab(const float* __restrict__ feat,
                                                const int* __restrict__ order,
                                                const int* __restrict__ parent) {
    extern __shared__ int sh[];
    int bid = blockIdx.x;
    int tid = threadIdx.x;

    if (bid < 6400) {
        __shared__ float t[32][33];
        int b = bid / 1600;
        int r2 = bid - b * 1600;
        int c0 = (r2 / 200) * 32;
        int n0 = (r2 % 200) * 32;
        int tx = tid & 31, ty = tid >> 5;
        const float* src = feat + ((size_t)b * CIN + c0) * Nn + n0;
#pragma unroll
        for (int r = 0; r < 32; r += 8)
            t[ty + r][tx] = src[(size_t)(ty + r) * Nn + tx];
        __syncthreads();
        float* dst = g_ft + ((size_t)b * Nn + n0) * CIN + c0;
#pragma unroll
        for (int r = 0; r < 32; r += 8)
            dst[(size_t)(ty + r) * CIN + tx] = t[tx][ty + r];
        return;
    }

    if (bid < 6404) {
        int* a0 = sh;
        int* a1 = sh + Nn;
        int* l0 = sh + 2 * Nn;
        int* l1 = sh + 3 * Nn;
        __shared__ int s_more;
        int b = bid - 6400;
        const int* pp = parent + b * Nn;
        const int* od = order + b * Nn;
        for (int k = tid; k < Nn; k += 256) {
            a0[k] = pp[k];
            l0[k] = (k == 0) ? 0 : 1;
            g_inv[b * Nn + od[k]] = k;
        }
        __syncthreads();
        int* aa = a0; int* ab = a1; int* la = l0; int* lb = l1;
        for (int it = 0; it < 13; ++it) {
            if (tid == 0) s_more = 0;
            __syncthreads();
            int any = 0;
            for (int k = tid; k < Nn; k += 256) {
                int a = aa[k];
                lb[k] = la[k] + la[a];
                int na = aa[a];
                ab[k] = na;
                any |= na;
            }
            if (any) s_more = 1;
            __syncthreads();
            int* tmp = aa; aa = ab; ab = tmp;
            tmp = la; la = lb; lb = tmp;
            if (!s_more) break;
        }
        int* ls = g_ls + b * (Nn + 2);
        for (int k = tid; k < Nn; k += 256) {
            if (k == 0) ls[0] = 0;
            else if (la[k] != la[k - 1]) ls[la[k]] = k;
            if (k == Nn - 1) { g_nlvl[b] = la[k] + 1; ls[la[k] + 1] = Nn; }
        }
        return;
    }

    // -------- tables role --------
    {
        int b = bid - 6404;
        const int* pp = parent + b * Nn;
        int*    anc = g_janc + (size_t)b * 5 * Nn;
        float4* jm4 = g_jm4  + (size_t)b * 5 * Nn;
        for (int k = tid; k < Nn; k += 256) {
            anc[k] = pp[k];
            float4 mv;
            mv.x = (k == 0) ? 0.f : g_w[((size_t)b * 4 + 0) * Nn + k];
            mv.y = (k == 0) ? 0.f : g_w[((size_t)b * 4 + 1) * Nn + k];
            mv.z = (k == 0) ? 0.f : g_w[((size_t)b * 4 + 2) * Nn + k];
            mv.w = (k == 0) ? 0.f : g_w[((size_t)b * 4 + 3) * Nn + k];
            jm4[k] = mv;
        }
        __syncthreads();
        for (int s = 1; s < 5; ++s) {
            for (int k = tid; k < Nn; k += 256) {
                int a = anc[(s - 1) * Nn + k];
                anc[s * Nn + k] = anc[(s - 1) * Nn + a];
                float4 mk = jm4[(s - 1) * Nn + k];
                float4 ma = jm4[(s - 1) * Nn + a];
                float4 mo;
                mo.x = mk.x * ma.x; mo.y = mk.y * ma.y;
                mo.z = mk.z * ma.z; mo.w = mk.w * ma.w;
                jm4[s * Nn + k] = mo;
            }
            __syncthreads();
        }
        float* jmP = g_jmP + (size_t)b * 5 * Gn * Nn;
        for (int s = 0; s < 5; ++s) {
            for (int k = tid; k < Nn; k += 256) {
                float4 m = jm4[s * Nn + k];
                jmP[(s * Gn + 0) * Nn + k] = m.x;
                jmP[(s * Gn + 1) * Nn + k] = m.y;
                jmP[(s * Gn + 2) * Nn + k] = m.z;
                jmP[(s * Gn + 3) * Nn + k] = m.w;
            }
        }
        int* rs = g_rs + (size_t)b * 5 * Nn;
        int* re = g_re + (size_t)b * 5 * Nn;
        for (int i = tid; i < 5 * Nn; i += 256) { rs[i] = 0; re[i] = 0; }
        __syncthreads();
        for (int s = 0; s < 5; ++s) {
            const int* as = anc + s * Nn;
            for (int j = tid; j < Nn; j += 256) {
                int a = as[j];
                int ap = (j > 0) ? as[j - 1] : -1;
                if (a != ap) {
                    rs[s * Nn + a] = j;
                    if (j > 0) re[s * Nn + ap] = j;
                }
                if (j == Nn - 1) re[s * Nn + a] = Nn;
            }
        }
    }
}

// ---------------- K4a: up-sweep, scalar chunks — register-primary values ----------------
__global__ __launch_bounds__(TU, 1) void k_upS(const int* __restrict__ order) {
    extern __shared__ float4 sm[];
    __shared__ int sls16[404];
    __shared__ int s_nlvl;
    int ci = blockIdx.x, b = blockIdx.y;
    int g = ci >> 4, qq = ci & 15;
    int tid = threadIdx.x;
    if (tid == 0) s_nlvl = g_nlvl[b];
    __syncthreads();
    int nlvl = s_nlvl;
    int nb16 = (nlvl + 15) / 16;
    const int* gls = g_ls + b * (Nn + 2);
    for (int i = tid; i <= nb16; i += TU) {
        int lev = 16 * i;
        sls16[i] = (lev == 0) ? 0 : ((lev >= nlvl) ? Nn : gls[lev]);
    }

    // init: values in registers
    const int* od = order + b * Nn;
    float4 val[QU];
    int ftcol = g * 64 + qq * 4;
#pragma unroll
    for (int q = 0; q < QU; ++q) {
        int k = tid + TU * q;
        if (k < Nn) {
            int n = od[k];
            float cf = g_conf[((size_t)b * Nn + n) * 4 + g];
            float4 v = *reinterpret_cast<const float4*>(g_ft + ((size_t)b * Nn + n) * CIN + ftcol);
            v.x *= cf; v.y *= cf; v.z *= cf; v.w *= cf;
            val[q] = v;
        } else val[q] = make_float4(0.f, 0.f, 0.f, 0.f);
    }

    const int*   rsb  = g_rs   + (size_t)b * 5 * Nn;
    const int*   reb  = g_re   + (size_t)b * 5 * Nn;
    const int*   ancb = g_janc + (size_t)b * 5 * Nn;
    const float* mPb  = g_jmP  + (size_t)b * 5 * Gn * Nn + (size_t)g * Nn;

    // ---- 4 factor passes: publish scaled, gather pure-LDS ----
#pragma unroll
    for (int s = 0; s < 4; ++s) {
        const float* mp = mPb + (size_t)s * Gn * Nn;
        const int* rs = rsb + s * Nn;
        const int* re = reb + s * Nn;
        float ms[QU];
#pragma unroll
        for (int q = 0; q < QU; ++q) {
            int k = tid + TU * q;
            ms[q] = (k < Nn) ? __ldg(&mp[k]) : 0.f;
        }
        __syncthreads();                   // close previous pass's sm reads
#pragma unroll
        for (int q = 0; q < QU; ++q) {
            int k = tid + TU * q;
            if (k < Nn) {
                float4 v = val[q]; float m = ms[q];
                sm[k] = make_float4(m * v.x, m * v.y, m * v.z, m * v.w);
            }
        }
        __syncthreads();
        int lo[QU], hi[QU];
#pragma unroll
        for (int q = 0; q < QU; ++q) {
            int k = tid + TU * q;
            if (k < Nn) { lo[q] = __ldg(&rs[k]); hi[q] = __ldg(&re[k]); }
            else        { lo[q] = 0; hi[q] = 0; }
        }
#pragma unroll
        for (int q = 0; q < QU; ++q) {
            float4 acc = val[q];
            for (int j = lo[q]; j < hi[q]; ++j) {
                float4 x = sm[j];
                acc.x += x.x; acc.y += x.y; acc.z += x.z; acc.w += x.w;
            }
            val[q] = acc;
        }
    }

    // ---- stride-16 tail solve, deep -> shallow ----
    {
        const int* rs4 = rsb + 4 * Nn;
        const int* re4 = reb + 4 * Nn;
        const float* m16 = mPb + (size_t)4 * Gn * Nn;
        float m16s[QU];
#pragma unroll
        for (int q = 0; q < QU; ++q) {
            int k = tid + TU * q;
            m16s[q] = (k < Nn) ? __ldg(&m16[k]) : 0.f;
        }
        __syncthreads();                   // close last factor gather
#pragma unroll
        for (int q = 0; q < QU; ++q) {
            int k = tid + TU * q;
            if (k < Nn) {
                float4 v = val[q]; float m = m16s[q];
                sm[k] = make_float4(m * v.x, m * v.y, m * v.z, m * v.w);
            }
        }
        __syncthreads();
        for (int blk = nb16 - 2; blk >= 0; --blk) {
            int s0 = sls16[blk], e0 = sls16[blk + 1];
#pragma unroll
            for (int q = 0; q < QU; ++q) {
                int k = tid + TU * q;
                if (k >= s0 && k < e0) {
                    float4 acc = val[q];
                    int lo = __ldg(&rs4[k]), hi = __ldg(&re4[k]);
                    for (int j = lo; j < hi; ++j) {
                        float4 x = sm[j];
                        acc.x += x.x; acc.y += x.y; acc.z += x.z; acc.w += x.w;
                    }
                    val[q] = acc;
                    float m = m16s[q];
                    sm[k] = make_float4(m * acc.x, m * acc.y, m * acc.z, m * acc.w);
                }
            }
            __syncthreads();
        }
    }

    // ---- c1 = (1 - w^2) * agg ----
#pragma unroll
    for (int q = 0; q < QU; ++q) {
        int k = tid + TU * q;
        if (k < Nn) {
            float w = __ldg(&mPb[k]);      // slot 0 = w
            float f = 1.f - w * w;
            val[q].x *= f; val[q].y *= f; val[q].z *= f; val[q].w *= f;
        }
    }

    // ---- compose passes: c2, c4, c8, c16 ----
#pragma unroll
    for (int s = 0; s < 4; ++s) {
        const int* anc = ancb + s * Nn;
        const float* mp = mPb + (size_t)s * Gn * Nn;
        __syncthreads();                   // close previous sm reads
#pragma unroll
        for (int q = 0; q < QU; ++q) {
            int k = tid + TU * q;
            if (k < Nn) sm[k] = val[q];
        }
        __syncthreads();
        int av[QU]; float ms[QU];
#pragma unroll
        for (int q = 0; q < QU; ++q) {
            int k = tid + TU * q;
            if (k < Nn) { av[q] = __ldg(&anc[k]); ms[q] = __ldg(&mp[k]); }
            else        { av[q] = 0; ms[q] = 0.f; }
        }
#pragma unroll
        for (int q = 0; q < QU; ++q) {
            int k = tid + TU * q;
            if (k < Nn) {
                float4 ca = sm[av[q]];
                float m = ms[q];
                val[q].x += m * ca.x; val[q].y += m * ca.y;
                val[q].z += m * ca.z; val[q].w += m * ca.w;
            }
        }
    }

    float4* cc = g_cC + ((size_t)b * NCH + ci) * Nn;
#pragma unroll
    for (int q = 0; q < QU; ++q) {
        int k = tid + TU * q;
        if (k < Nn) cc[k] = val[q];
    }
}

// ---------------- K4b: up-sweep, norm chunk (float4 multipliers) ----------------
__global__ __launch_bounds__(TU, 1) void k_upN(const int* __restrict__ order) {
    extern __shared__ float4 sm[];
    __shared__ int sls16[404];
    __shared__ int s_nlvl;
    int b = blockIdx.y;
    int tid = threadIdx.x;
    if (tid == 0) s_nlvl = g_nlvl[b];
    __syncthreads();
    int nlvl = s_nlvl;
    int nb16 = (nlvl + 15) / 16;
    const int* gls = g_ls + b * (Nn + 2);
    for (int i = tid; i <= nb16; i += TU) {
        int lev = 16 * i;
        sls16[i] = (lev == 0) ? 0 : ((lev >= nlvl) ? Nn : gls[lev]);
    }

    const int* od = order + b * Nn;
    float4 val[QU];
#pragma unroll
    for (int q = 0; q < QU; ++q) {
        int k = tid + TU * q;
        if (k < Nn) {
            int n = od[k];
            val[q] = *reinterpret_cast<const float4*>(g_conf + ((size_t)b * Nn + n) * 4);
        } else val[q] = make_float4(0.f, 0.f, 0.f, 0.f);
    }

    const int*    rsb  = g_rs   + (size_t)b * 5 * Nn;
    const int*    reb  = g_re   + (size_t)b * 5 * Nn;
    const int*    ancb = g_janc + (size_t)b * 5 * Nn;
    const float4* m4b  = g_jm4  + (size_t)b * 5 * Nn;

    for (int s = 0; s < 4; ++s) {
        const float4* mp = m4b + s * Nn;
        const int* rs = rsb + s * Nn;
        const int* re = reb + s * Nn;
        __syncthreads();
#pragma unroll
        for (int q = 0; q < QU; ++q) {
            int k = tid + TU * q;
            if (k < Nn) {
                float4 v = val[q];
                float4 m = __ldg(&mp[k]);
                sm[k] = make_float4(m.x * v.x, m.y * v.y, m.z * v.z, m.w * v.w);
            }
        }
        __syncthreads();
#pragma unroll
        for (int q = 0; q < QU; ++q) {
            int k = tid + TU * q;
            if (k < Nn) {
                float4 acc = val[q];
                int lo = __ldg(&rs[k]), hi = __ldg(&re[k]);
                for (int j = lo; j < hi; ++j) {
                    float4 x = sm[j];
                    acc.x += x.x; acc.y += x.y; acc.z += x.z; acc.w += x.w;
                }
                val[q] = acc;
            }
        }
    }

    // tail
    {
        const int* rs4 = rsb + 4 * Nn;
        const int* re4 = reb + 4 * Nn;
        const float4* m16 = m4b + 4 * Nn;
        __syncthreads();
#pragma unroll
        for (int q = 0; q < QU; ++q) {
            int k = tid + TU * q;
            if (k < Nn) {
                float4 v = val[q];
                float4 m = __ldg(&m16[k]);
                sm[k] = make_float4(m.x * v.x, m.y * v.y, m.z * v.z, m.w * v.w);
            }
        }
        __syncthreads();
        for (int blk = nb16 - 2; blk >= 0; --blk) {
            int s0 = sls16[blk], e0 = sls16[blk + 1];
#pragma unroll
            for (int q = 0; q < QU; ++q) {
                int k = tid + TU * q;
                if (k >= s0 && k < e0) {
                    float4 acc = val[q];
                    int lo = __ldg(&rs4[k]), hi = __ldg(&re4[k]);
                    for (int j = lo; j < hi; ++j) {
                        float4 x = sm[j];
                        acc.x += x.x; acc.y += x.y; acc.z += x.z; acc.w += x.w;
                    }
                    val[q] = acc;
                    float4 m = __ldg(&m16[k]);
                    sm[k] = make_float4(m.x * acc.x, m.y * acc.y, m.z * acc.z, m.w * acc.w);
                }
            }
            __syncthreads();
        }
    }

    // c1
#pragma unroll
    for (int q = 0; q < QU; ++q) {
        int k = tid + TU * q;
        if (k < Nn) {
            float4 w = __ldg(&m4b[k]);
            val[q].x *= 1.f - w.x * w.x; val[q].y *= 1.f - w.y * w.y;
            val[q].z *= 1.f - w.z * w.z; val[q].w *= 1.f - w.w * w.w;
        }
    }

    // compose
    for (int s = 0; s < 4; ++s) {
        const int* anc = ancb + s * Nn;
        const float4* mp = m4b + s * Nn;
        __syncthreads();
#pragma unroll
        for (int q = 0; q < QU; ++q) {
            int k = tid + TU * q;
            if (k < Nn) sm[k] = val[q];
        }
        __syncthreads();
#pragma unroll
        for (int q = 0; q < QU; ++q) {
            int k = tid + TU * q;
            if (k < Nn) {
                float4 ca = sm[__ldg(&anc[k])];
                float4 m = __ldg(&mp[k]);
                val[q].x += m.x * ca.x; val[q].y += m.y * ca.y;
                val[q].z += m.z * ca.z; val[q].w += m.w * ca.w;
            }
        }
    }

    float4* cc = g_cC + ((size_t)b * NCH + 64) * Nn;
#pragma unroll
    for (int q = 0; q < QU; ++q) {
        int k = tid + TU * q;
        if (k < Nn) cc[k] = val[q];
    }
}

// ---------------- K5: strided down-sweep (16 levels per phase) ----------------
__global__ __launch_bounds__(TU, 2) void k_down() {
    extern __shared__ float4 Z[];
    __shared__ int sls16[404];
    __shared__ int s_nlvl;
    int ci = blockIdx.x, b = blockIdx.y;
    int tid = threadIdx.x;
    bool norm = (ci == 64);
    int g = norm ? 0 : (ci >> 4);

    if (tid == 0) s_nlvl = g_nlvl[b];
    __syncthreads();
    int nlvl = s_nlvl;
    int nph = (nlvl + 15) / 16;
    const int* gls = g_ls + b * (Nn + 2);
    for (int i = tid; i <= nph; i += TU) {
        int lev = 16 * i;
        sls16[i] = (lev == 0) ? 0 : ((lev >= nlvl) ? Nn : gls[lev]);
    }
    __syncthreads();

    float4* cc = g_cC + ((size_t)b * NCH + ci) * Nn;
    const int* aa = g_janc + ((size_t)b * 5 + 4) * Nn;
    const float4* m4 = g_jm4 + ((size_t)b * 5 + 4) * Nn;
    const float* mP = g_jmP + (size_t)b * 5 * Gn * Nn + (size_t)(4 * Gn + g) * Nn;

    for (int t = 0; t < nph; ++t) {
        int s0 = sls16[t], e0 = sls16[t + 1];
        for (int k = s0 + tid; k < e0; k += TU) {
            float4 cv = __ldg(&cc[k]);
            if (t > 0) {
                int a = __ldg(&aa[k]);
                float4 zp = Z[a];
                if (!norm) {
                    float m = __ldg(&mP[k]);
                    cv.x += m * zp.x; cv.y += m * zp.y;
                    cv.z += m * zp.z; cv.w += m * zp.w;
                } else {
                    float4 m = __ldg(&m4[k]);
                    cv.x += m.x * zp.x; cv.y += m.y * zp.y;
                    cv.z += m.z * zp.z; cv.w += m.w * zp.w;
                }
            }
            Z[k] = cv;
        }
        __syncthreads();
    }
    for (int k = tid; k < Nn; k += TU) cc[k] = Z[k];
}

// ---------------- K6: normalize + un-permute + residual ----------------
__global__ __launch_bounds__(256) void k_final(const float* __restrict__ feat,
                                               const float* __restrict__ gammap,
                                               float* __restrict__ out) {
    __shared__ float tile[32 * 65 * 4];
    __shared__ int kq[32];
    int b = blockIdx.y, n0 = blockIdx.x * 32;
    int tid = threadIdx.x;
    if (tid < 32) kq[tid] = g_inv[b * Nn + n0 + tid];
    __syncthreads();
    float4* tile4 = reinterpret_cast<float4*>(tile);
    for (int i = tid; i < 32 * 65; i += 256) {
        int r = i / 65, ci = i - r * 65;
        tile4[i] = g_cC[((size_t)b * NCH + ci) * Nn + kq[r]];
    }
    __syncthreads();
    float gamma = gammap[0];
    int nl = tid & 31;
    int cg = tid >> 5;
    for (int c = cg; c < 256; c += 8) {
        int gr = c >> 6, j = c & 63;
        float filt = tile[(nl * 65 + gr * 16 + (j >> 2)) * 4 + (j & 3)];
        float nrm  = tile[(nl * 65 + 64) * 4 + gr];
        float res = filt / (EPSV + nrm);
        size_t idx = ((size_t)b * CIN + c) * Nn + n0 + nl;
        out[idx] = fmaf(gamma, res, feat[idx]);
    }
}

// ---------------- launcher ----------------
extern "C" void kernel_launch(void* const* d_in, const int* in_sizes, int n_in,
                              void* d_out, int out_size) {
    const float* feature = (const float*)d_in[0];
    const float* guide   = (const float*)d_in[1];
    const float* We      = (const float*)d_in[2];
    const float* Wc      = (const float*)d_in[3];
    const float* Wg      = (const float*)d_in[4];
    const float* beta    = (const float*)d_in[5];
    const float* gamma   = (const float*)d_in[6];
    const int*   order   = (const int*)d_in[7];
    const int*   parent  = (const int*)d_in[8];
    float* out = (float*)d_out;

    cudaFuncSetAttribute(k_pretab, cudaFuncAttributeMaxDynamicSharedMemorySize, 4 * Nn * 4);
    cudaFuncSetAttribute(k_upS,    cudaFuncAttributeMaxDynamicSharedMemorySize, Nn * 16);
    cudaFuncSetAttribute(k_upN,    cudaFuncAttributeMaxDynamicSharedMemorySize, Nn * 16);
    cudaFuncSetAttribute(k_down,   cudaFuncAttributeMaxDynamicSharedMemorySize, Nn * 16);

    // k_upS is this module's 4th launch (ncu -s 5 profiles it)
    k_gemm<<<dim3(Nn / 128, Bn, 2), 256>>>(feature, guide, We, Wc, Wg);
    k_w<<<dim3(Nn * 2 / 256, Bn), 256>>>(order, parent, beta);
    k_pretab<<<6408, 256, 4 * Nn * 4>>>(feature, order, parent);
    k_upS<<<dim3(64, Bn), TU, Nn * 16>>>(order);
    k_upN<<<dim3(1, Bn), TU, Nn * 16>>>(order);
    k_down<<<dim3(NCH, Bn), TU, Nn * 16>>>();
    k_final<<<dim3(Nn / 32, Bn), 256>>>(feature, gamma, out);
}